// round 1
// baseline (speedup 1.0000x reference)
#include <cuda_runtime.h>
#include <cstdint>
#include <cstddef>

#define HW    9216      // 96*96
#define T_DIM 32
#define B_DIM 2
#define C_ENC 64
#define HID   256
#define NCELL (B_DIM * T_DIM * HW)   // 589824

// Scratch (device globals — allocation-free per harness rules)
__device__ float g_xenc[(size_t)NCELL * C_ENC];   // conv output, channels-last  (151 MB)
__device__ float g_A[(size_t)NCELL * HID];        // 30*(xenc @ W1[0:64] + b1)   (604 MB)

// ---------------------------------------------------------------------------
// Kernel 1: 3D conv (2 -> 64 channels, 3x3x3, SAME), output channels-last.
// One thread = one output pixel (all 64 channels). Weights in smem.
// ---------------------------------------------------------------------------
__global__ __launch_bounds__(256) void conv_kernel(
    const float* __restrict__ xr, const float* __restrict__ xi,
    const float* __restrict__ ew, const float* __restrict__ eb)
{
    extern __shared__ float sm[];
    float* ws   = sm;            // 3456 = 64*2*27
    float* bs   = ws + 3456;     // 64
    float* tile = bs + 64;       // 256 * 65

    int tid = threadIdx.x;
    for (int e = tid; e < 3456; e += 256) ws[e] = ew[e];
    if (tid < 64) bs[tid] = eb[tid];

    int blk  = blockIdx.x;
    int bt   = blk / 36;          // (b*32 + t)
    int t36  = blk % 36;
    int t    = bt & 31;
    int b    = bt >> 5;
    int pix  = t36 * 256 + tid;   // < 9216
    int h    = pix / 96;
    int w    = pix % 96;

    float v[54];
    {
        int e = 0;
        #pragma unroll
        for (int ch = 0; ch < 2; ch++) {
            const float* src = (ch == 0) ? xr : xi;
            #pragma unroll
            for (int dt = -1; dt <= 1; dt++) {
                int  tt  = t + dt;
                bool okt = (tt >= 0) && (tt < 32);
                #pragma unroll
                for (int dh = -1; dh <= 1; dh++) {
                    int  hh  = h + dh;
                    bool okh = okt && (hh >= 0) && (hh < 96);
                    #pragma unroll
                    for (int dw = -1; dw <= 1; dw++) {
                        int  ww = w + dw;
                        bool ok = okh && (ww >= 0) && (ww < 96);
                        v[e++] = ok ? src[(((size_t)(b * 32 + tt)) * 96 + hh) * 96 + ww] : 0.0f;
                    }
                }
            }
        }
    }
    __syncthreads();

    #pragma unroll 4
    for (int c = 0; c < 64; c++) {
        float acc = bs[c];
        #pragma unroll
        for (int q = 0; q < 54; q++) acc = fmaf(v[q], ws[c * 54 + q], acc);
        tile[tid * 65 + c] = acc;   // padded -> conflict-free writes
    }
    __syncthreads();

    size_t outbase = ((size_t)bt * HW + (size_t)t36 * 256) * 64;
    for (int e = tid; e < 256 * 64; e += 256) {
        int p = e >> 6, c = e & 63;
        g_xenc[outbase + e] = tile[p * 65 + c];
    }
}

// ---------------------------------------------------------------------------
// Kernel 2: A = 30 * (xenc @ W1[0:64,:] + b1)   [589824 x 64] @ [64 x 256]
// Block: 64 cells x 256 cols, 256 threads, 4x16 register tile each.
// ---------------------------------------------------------------------------
__global__ __launch_bounds__(256) void proj_kernel(
    const float* __restrict__ W1, const float* __restrict__ b1)
{
    extern __shared__ float sm[];
    float* xeT = sm;             // [64 k][68 row-pad]
    float* w1s = sm + 64 * 68;   // [64][256]

    int    tid   = threadIdx.x;
    size_t cell0 = (size_t)blockIdx.x * 64;

    for (int e = tid; e < 64 * 256 / 4; e += 256)
        ((float4*)w1s)[e] = ((const float4*)W1)[e];

    {
        int k = tid & 63, rr = tid >> 6;
        #pragma unroll
        for (int r0 = 0; r0 < 64; r0 += 4) {
            int r = r0 + rr;
            xeT[k * 68 + r] = g_xenc[(cell0 + r) * 64 + k];
        }
    }
    __syncthreads();

    int   j = tid & 15, i = tid >> 4;   // col group j (16 cols), row group i (4 rows)
    float acc[4][16];
    #pragma unroll
    for (int m = 0; m < 4; m++)
        #pragma unroll
        for (int n = 0; n < 16; n++) acc[m][n] = 0.0f;

    #pragma unroll 4
    for (int k = 0; k < 64; k++) {
        float4 av = *(const float4*)&xeT[k * 68 + 4 * i];
        float  a[4] = {av.x, av.y, av.z, av.w};
        float  bb[16];
        #pragma unroll
        for (int c4 = 0; c4 < 4; c4++) {
            float4 bv = *(const float4*)&w1s[k * 256 + 16 * j + 4 * c4];
            bb[4*c4+0] = bv.x; bb[4*c4+1] = bv.y; bb[4*c4+2] = bv.z; bb[4*c4+3] = bv.w;
        }
        #pragma unroll
        for (int m = 0; m < 4; m++)
            #pragma unroll
            for (int n = 0; n < 16; n++)
                acc[m][n] = fmaf(a[m], bb[n], acc[m][n]);
    }

    float b1v[16];
    #pragma unroll
    for (int c4 = 0; c4 < 4; c4++) {
        float4 bv = *(const float4*)&b1[16 * j + 4 * c4];
        b1v[4*c4+0] = bv.x; b1v[4*c4+1] = bv.y; b1v[4*c4+2] = bv.z; b1v[4*c4+3] = bv.w;
    }
    #pragma unroll
    for (int m = 0; m < 4; m++) {
        size_t row = cell0 + 4 * i + m;
        float* dst = &g_A[row * 256 + 16 * j];
        #pragma unroll
        for (int c4 = 0; c4 < 4; c4++) {
            float4 o;
            o.x = 30.0f * (acc[m][4*c4+0] + b1v[4*c4+0]);
            o.y = 30.0f * (acc[m][4*c4+1] + b1v[4*c4+1]);
            o.z = 30.0f * (acc[m][4*c4+2] + b1v[4*c4+2]);
            o.w = 30.0f * (acc[m][4*c4+3] + b1v[4*c4+3]);
            ((float4*)dst)[c4] = o;
        }
    }
}

// ---------------------------------------------------------------------------
// Kernel 3: fused SIREN per (b, q, 64-pixel tile):
//   rows 0..63 = floor eval, rows 64..127 = ceil eval (M=128, N=256, K=256)
//   h1 = sin(A + 30*tc*W1[64,:]) ; z2 = h1@W2 ; h2 = sin(30*z2 + 30*b2)
//   out = lerp(h2f@W3, h2c@W3, tau) + b3
// 512 threads, each 4x16 fp32 register tile. W2 staged in smem by K=64 tiles.
// ---------------------------------------------------------------------------
__global__ __launch_bounds__(512) void main_kernel(
    const float* __restrict__ tcoord, const float* __restrict__ W1,
    const float* __restrict__ W2, const float* __restrict__ b2,
    const float* __restrict__ W3, const float* __restrict__ b3,
    float* __restrict__ out)
{
    extern __shared__ float sm[];
    float* h1     = sm;               // [256 k][132 row-pad]  (rows = 128 evals)
    float* w2s    = sm + 256 * 132;   // [64][256]
    float* rowres = w2s + 64 * 256;   // [128]

    int tid  = threadIdx.x;
    int bq   = blockIdx.y;            // b*32 + q
    int b    = bq >> 5;
    int pix0 = blockIdx.x * 64;

    float tc = tcoord[bq];
    tc = fminf(fmaxf(tc, -1.0f), 1.0f - 1e-6f);
    const float df = 2.0f / 31.0f;
    int   ti  = (int)floorf((tc + 1.0f) / df);
    float tau = (tc - (-1.0f + (float)ti * df)) / df;
    float ctc = 30.0f * tc;

    const float* Af = g_A + ((size_t)(b * 32 + ti) * HW + pix0) * 256;

    // Phase 1: h1 (transposed [k][row]) for both evals
    {
        int   k  = tid & 255;
        int   rr = tid >> 8;                    // 0 or 1
        float wk = W1[64 * 256 + k] * ctc;
        #pragma unroll 4
        for (int r0 = 0; r0 < 128; r0 += 2) {
            int r = r0 + rr;
            size_t off = (r < 64) ? ((size_t)r * 256)
                                  : ((size_t)HW * 256 + (size_t)(r - 64) * 256);
            h1[k * 132 + r] = __sinf(Af[off + k] + wk);
        }
    }

    int   j = tid & 15;    // col group: 16 cols
    int   i = tid >> 4;    // row group 0..31: 4 rows
    float acc[4][16];
    #pragma unroll
    for (int m = 0; m < 4; m++)
        #pragma unroll
        for (int n = 0; n < 16; n++) acc[m][n] = 0.0f;

    for (int kb = 0; kb < 256; kb += 64) {
        __syncthreads();   // also covers phase-1 completion on first iter
        for (int e = tid; e < 64 * 256 / 4; e += 512)
            ((float4*)w2s)[e] = ((const float4*)(W2 + (size_t)kb * 256))[e];
        __syncthreads();

        #pragma unroll 4
        for (int kk = 0; kk < 64; kk++) {
            float4 av = *(const float4*)&h1[(kb + kk) * 132 + 4 * i];
            float  a[4] = {av.x, av.y, av.z, av.w};
            float  bb[16];
            #pragma unroll
            for (int c4 = 0; c4 < 4; c4++) {
                float4 bv = *(const float4*)&w2s[kk * 256 + 16 * j + 4 * c4];
                bb[4*c4+0] = bv.x; bb[4*c4+1] = bv.y; bb[4*c4+2] = bv.z; bb[4*c4+3] = bv.w;
            }
            #pragma unroll
            for (int m = 0; m < 4; m++)
                #pragma unroll
                for (int n = 0; n < 16; n++)
                    acc[m][n] = fmaf(a[m], bb[n], acc[m][n]);
        }
    }

    // Epilogue: h2 = sin(30*z2 + 30*b2), layer-3 partial dot, shuffle-reduce over j
    float w3v[16], b2v[16];
    #pragma unroll
    for (int c4 = 0; c4 < 4; c4++) {
        float4 wv = *(const float4*)&W3[16 * j + 4 * c4];
        float4 bv = *(const float4*)&b2[16 * j + 4 * c4];
        w3v[4*c4+0] = wv.x; w3v[4*c4+1] = wv.y; w3v[4*c4+2] = wv.z; w3v[4*c4+3] = wv.w;
        b2v[4*c4+0] = 30.0f*bv.x; b2v[4*c4+1] = 30.0f*bv.y;
        b2v[4*c4+2] = 30.0f*bv.z; b2v[4*c4+3] = 30.0f*bv.w;
    }
    float part[4];
    #pragma unroll
    for (int m = 0; m < 4; m++) {
        float s = 0.0f;
        #pragma unroll
        for (int n = 0; n < 16; n++)
            s = fmaf(__sinf(fmaf(30.0f, acc[m][n], b2v[n])), w3v[n], s);
        part[m] = s;
    }
    #pragma unroll
    for (int msk = 8; msk; msk >>= 1) {
        #pragma unroll
        for (int m = 0; m < 4; m++)
            part[m] += __shfl_xor_sync(0xffffffffu, part[m], msk);
    }
    if (j == 0) {
        #pragma unroll
        for (int m = 0; m < 4; m++) rowres[4 * i + m] = part[m];
    }
    __syncthreads();

    if (tid < 64) {
        float zf = rowres[tid];
        float zc = rowres[64 + tid];
        out[(size_t)bq * HW + pix0 + tid] = fmaf(tau, zc - zf, zf) + b3[0];
    }
}

// ---------------------------------------------------------------------------
extern "C" void kernel_launch(void* const* d_in, const int* in_sizes, int n_in,
                              void* d_out, int out_size)
{
    const float* x_real  = (const float*)d_in[0];
    const float* x_imag  = (const float*)d_in[1];
    const float* t_coord = (const float*)d_in[2];
    const float* enc_w   = (const float*)d_in[3];
    const float* enc_b   = (const float*)d_in[4];
    const float* W1      = (const float*)d_in[5];
    const float* b1      = (const float*)d_in[6];
    const float* W2      = (const float*)d_in[7];
    const float* b2      = (const float*)d_in[8];
    const float* W3      = (const float*)d_in[9];
    const float* b3      = (const float*)d_in[10];
    float*       out     = (float*)d_out;

    size_t smem1 = (3456 + 64 + 256 * 65) * sizeof(float);        //  80,640 B
    size_t smem2 = (64 * 68 + 64 * 256) * sizeof(float);          //  82,944 B
    size_t smem3 = (256 * 132 + 64 * 256 + 128) * sizeof(float);  // 201,216 B
    cudaFuncSetAttribute(conv_kernel, cudaFuncAttributeMaxDynamicSharedMemorySize, (int)smem1);
    cudaFuncSetAttribute(proj_kernel, cudaFuncAttributeMaxDynamicSharedMemorySize, (int)smem2);
    cudaFuncSetAttribute(main_kernel, cudaFuncAttributeMaxDynamicSharedMemorySize, (int)smem3);

    conv_kernel<<<2304, 256, smem1>>>(x_real, x_imag, enc_w, enc_b);
    proj_kernel<<<9216, 256, smem2>>>(W1, b1);
    main_kernel<<<dim3(144, 64), 512, smem3>>>(t_coord, W1, W2, b2, W3, b3, out);
}

// round 5
// speedup vs baseline: 3.9453x; 3.9453x over previous
#include <cuda_runtime.h>
#include <cuda_fp16.h>
#include <cstdint>
#include <cstddef>

#define HW    9216      // 96*96
#define NCELL (2 * 32 * HW)   // 589824

// Scratch (device globals — allocation-free per harness rules)
__device__ float g_xenc[(size_t)NCELL * 64];    // conv output, channels-last
__device__ float g_A[(size_t)NCELL * 256];      // 30*(xenc @ W1[0:64] + b1)
__device__ __align__(16) __half g_w2h[256 * 264];  // W2^T fp16, [n][k] padded rows (264)

// ---------------------------------------------------------------------------
// Helpers
// ---------------------------------------------------------------------------
__device__ __forceinline__ uint32_t smem_u32(const void* p) {
    uint32_t a;
    asm("{ .reg .u64 t; cvta.to.shared.u64 t, %1; cvt.u32.u64 %0, t; }" : "=r"(a) : "l"(p));
    return a;
}
__device__ __forceinline__ void ldsm_x4(uint32_t (&r)[4], uint32_t addr) {
    asm volatile("ldmatrix.sync.aligned.m8n8.x4.shared.b16 {%0,%1,%2,%3}, [%4];"
                 : "=r"(r[0]), "=r"(r[1]), "=r"(r[2]), "=r"(r[3]) : "r"(addr));
}
__device__ __forceinline__ void mma16816(float (&d)[4], const uint32_t (&a)[4],
                                         const uint32_t* b) {
    asm volatile("mma.sync.aligned.m16n8k16.row.col.f32.f16.f16.f32 "
                 "{%0,%1,%2,%3}, {%4,%5,%6,%7}, {%8,%9}, {%0,%1,%2,%3};"
                 : "+f"(d[0]), "+f"(d[1]), "+f"(d[2]), "+f"(d[3])
                 : "r"(a[0]), "r"(a[1]), "r"(a[2]), "r"(a[3]), "r"(b[0]), "r"(b[1]));
}

// ---------------------------------------------------------------------------
// Kernel 1: 3D conv (2 -> 64 channels, 3x3x3, SAME), output channels-last.
// ---------------------------------------------------------------------------
__global__ __launch_bounds__(256) void conv_kernel(
    const float* __restrict__ xr, const float* __restrict__ xi,
    const float* __restrict__ ew, const float* __restrict__ eb)
{
    extern __shared__ float sm[];
    float* ws   = sm;            // 3456
    float* bs   = ws + 3456;     // 64
    float* tile = bs + 64;       // 256 * 65

    int tid = threadIdx.x;
    for (int e = tid; e < 3456; e += 256) ws[e] = ew[e];
    if (tid < 64) bs[tid] = eb[tid];

    int blk = blockIdx.x;
    int bt  = blk / 36;
    int t36 = blk % 36;
    int t   = bt & 31;
    int b   = bt >> 5;
    int pix = t36 * 256 + tid;
    int h   = pix / 96;
    int w   = pix % 96;

    float v[54];
    {
        int e = 0;
        #pragma unroll
        for (int ch = 0; ch < 2; ch++) {
            const float* src = (ch == 0) ? xr : xi;
            #pragma unroll
            for (int dt = -1; dt <= 1; dt++) {
                int  tt  = t + dt;
                bool okt = (tt >= 0) && (tt < 32);
                #pragma unroll
                for (int dh = -1; dh <= 1; dh++) {
                    int  hh  = h + dh;
                    bool okh = okt && (hh >= 0) && (hh < 96);
                    #pragma unroll
                    for (int dw = -1; dw <= 1; dw++) {
                        int  ww = w + dw;
                        bool ok = okh && (ww >= 0) && (ww < 96);
                        v[e++] = ok ? src[(((size_t)(b * 32 + tt)) * 96 + hh) * 96 + ww] : 0.0f;
                    }
                }
            }
        }
    }
    __syncthreads();

    #pragma unroll 4
    for (int c = 0; c < 64; c++) {
        float acc = bs[c];
        #pragma unroll
        for (int q = 0; q < 54; q++) acc = fmaf(v[q], ws[c * 54 + q], acc);
        tile[tid * 65 + c] = acc;
    }
    __syncthreads();

    size_t outbase = ((size_t)bt * HW + (size_t)t36 * 256) * 64;
    for (int e = tid; e < 256 * 64; e += 256) {
        int p = e >> 6, c = e & 63;
        g_xenc[outbase + e] = tile[p * 65 + c];
    }
}

// ---------------------------------------------------------------------------
// Kernel 2: A = 30 * (xenc @ W1[0:64,:] + b1)
// ---------------------------------------------------------------------------
__global__ __launch_bounds__(256) void proj_kernel(
    const float* __restrict__ W1, const float* __restrict__ b1)
{
    extern __shared__ float sm[];
    float* xeT = sm;             // [64 k][68 pad]
    float* w1s = sm + 64 * 68;   // [64][256]

    int    tid   = threadIdx.x;
    size_t cell0 = (size_t)blockIdx.x * 64;

    for (int e = tid; e < 64 * 256 / 4; e += 256)
        ((float4*)w1s)[e] = ((const float4*)W1)[e];

    {
        int k = tid & 63, rr = tid >> 6;
        #pragma unroll
        for (int r0 = 0; r0 < 64; r0 += 4) {
            int r = r0 + rr;
            xeT[k * 68 + r] = g_xenc[(cell0 + r) * 64 + k];
        }
    }
    __syncthreads();

    int   j = tid & 15, i = tid >> 4;
    float acc[4][16];
    #pragma unroll
    for (int m = 0; m < 4; m++)
        #pragma unroll
        for (int n = 0; n < 16; n++) acc[m][n] = 0.0f;

    #pragma unroll 4
    for (int k = 0; k < 64; k++) {
        float4 av = *(const float4*)&xeT[k * 68 + 4 * i];
        float  a[4] = {av.x, av.y, av.z, av.w};
        float  bb[16];
        #pragma unroll
        for (int c4 = 0; c4 < 4; c4++) {
            float4 bv = *(const float4*)&w1s[k * 256 + 16 * j + 4 * c4];
            bb[4*c4+0] = bv.x; bb[4*c4+1] = bv.y; bb[4*c4+2] = bv.z; bb[4*c4+3] = bv.w;
        }
        #pragma unroll
        for (int m = 0; m < 4; m++)
            #pragma unroll
            for (int n = 0; n < 16; n++)
                acc[m][n] = fmaf(a[m], bb[n], acc[m][n]);
    }

    float b1v[16];
    #pragma unroll
    for (int c4 = 0; c4 < 4; c4++) {
        float4 bv = *(const float4*)&b1[16 * j + 4 * c4];
        b1v[4*c4+0] = bv.x; b1v[4*c4+1] = bv.y; b1v[4*c4+2] = bv.z; b1v[4*c4+3] = bv.w;
    }
    #pragma unroll
    for (int m = 0; m < 4; m++) {
        size_t row = cell0 + 4 * i + m;
        float* dst = &g_A[row * 256 + 16 * j];
        #pragma unroll
        for (int c4 = 0; c4 < 4; c4++) {
            float4 o;
            o.x = 30.0f * (acc[m][4*c4+0] + b1v[4*c4+0]);
            o.y = 30.0f * (acc[m][4*c4+1] + b1v[4*c4+1]);
            o.z = 30.0f * (acc[m][4*c4+2] + b1v[4*c4+2]);
            o.w = 30.0f * (acc[m][4*c4+3] + b1v[4*c4+3]);
            ((float4*)dst)[c4] = o;
        }
    }
}

// ---------------------------------------------------------------------------
// Kernel prep: W2^T -> fp16, [n][k] rows padded to 264 halves
// ---------------------------------------------------------------------------
__global__ void prep_w2(const float* __restrict__ W2)
{
    int idx = blockIdx.x * 256 + threadIdx.x;   // 65536 total
    int n = idx >> 8, k = idx & 255;
    g_w2h[n * 264 + k] = __float2half_rn(W2[k * 256 + n]);
}

// ---------------------------------------------------------------------------
// Kernel 3: persistent HMMA SIREN.
// Per tile (bq, 64 pixels), two halves: half0 = floor eval, half1 = ceil eval.
// D[64x256 f32] = A_hi[64x256 f16] @ W2f + A_lo @ W2f   (mma.sync m16n8k16)
// ---------------------------------------------------------------------------
#define AROW   528            // bytes per A/B smem row (264 halves)
#define SM_B    0             // 256 * 528 = 135168
#define SM_AHI  135168        // 64 * 528  =  33792
#define SM_ALO  168960        // 64 * 528  =  33792
#define SM_W1T  202752        // 1024
#define SM_B2   203776        // 1024 (unused slack)
#define SM_W3   204800        // 1024 (unused slack)
#define SM_SLOT 205824        // 4 * 64 * 4 = 1024
#define SM_TOT  206848

__global__ __launch_bounds__(256, 1) void main_kernel(
    const float* __restrict__ tcoord, const float* __restrict__ W1,
    const float* __restrict__ b2, const float* __restrict__ W3,
    const float* __restrict__ b3, float* __restrict__ out)
{
    extern __shared__ char smem[];
    const uint32_t sb = smem_u32(smem);
    int tid  = threadIdx.x;
    int w    = tid >> 5;
    int lane = tid & 31;

    // Stage W2 fp16 (prebuilt padded rows) — resident for whole kernel
    {
        const float4* src = (const float4*)g_w2h;
        float4*       dst = (float4*)(smem + SM_B);
        for (int i = tid; i < 256 * 528 / 16; i += 256) dst[i] = src[i];
    }
    float* w1t   = (float*)(smem + SM_W1T);
    float* slots = (float*)(smem + SM_SLOT);
    if (tid < 256) w1t[tid] = W1[64 * 256 + tid];
    __syncthreads();

    const float b3v = b3[0];

    // Warp tiling: m-group = w&1 (32 rows), n-group = w>>1 (64 cols)
    const int wm = (w & 1) * 32;
    const int wn = (w >> 1) * 64;
    const int ng = w >> 1;

    // Per-thread epilogue constants (n coords fixed for the whole kernel)
    float b2r[16], w3r[16];
    #pragma unroll
    for (int q = 0; q < 16; q++) {
        int n = wn + (q >> 1) * 8 + (lane & 3) * 2 + (q & 1);
        b2r[q] = 30.0f * b2[n];
        w3r[q] = W3[n];
    }

    // ldmatrix per-thread byte offsets
    const uint32_t a_toff = (uint32_t)(wm + (lane & 15)) * AROW + (uint32_t)(lane >> 4) * 16;
    const uint32_t b_toff = (uint32_t)(wn + (lane & 7) + ((lane >> 4) & 1) * 8) * AROW
                          + (uint32_t)((lane >> 3) & 1) * 16;
    const uint32_t b_base = sb + SM_B + b_toff;

    const int p1row = tid >> 2;          // phase-1: row this thread fills
    const int p1k   = (tid & 3) * 64;    // phase-1: k range start

    for (int tile = blockIdx.x; tile < 9216; tile += 148) {
        int bq = tile & 63, pt = tile >> 6;
        int b  = bq >> 5,  pix0 = pt * 64;

        float tc = tcoord[bq];
        tc = fminf(fmaxf(tc, -1.0f), 1.0f - 1e-6f);
        const float df = 2.0f / 31.0f;
        int   ti  = (int)floorf((tc + 1.0f) / df);
        float tau = (tc - (-1.0f + (float)ti * df)) / df;
        float ctc = 30.0f * tc;

        float zhalf[2];
        #pragma unroll 1
        for (int h = 0; h < 2; h++) {
            // ---- Phase 1: h1 = sin(A + ctc*w1t), fp16 hi/lo into smem ----
            {
                const float4* s4 = (const float4*)(
                    g_A + ((size_t)(b * 32 + ti + h) * HW + pix0 + p1row) * 256 + p1k);
                char* hi_base = smem + SM_AHI + p1row * AROW + p1k * 2;
                char* lo_base = smem + SM_ALO + p1row * AROW + p1k * 2;
                #pragma unroll
                for (int j = 0; j < 16; j++) {
                    float4 a4 = s4[j];
                    const float4 w4 = *(const float4*)&w1t[p1k + 4 * j];
                    float s0 = __sinf(fmaf(ctc, w4.x, a4.x));
                    float s1 = __sinf(fmaf(ctc, w4.y, a4.y));
                    float s2 = __sinf(fmaf(ctc, w4.z, a4.z));
                    float s3 = __sinf(fmaf(ctc, w4.w, a4.w));
                    __half h0 = __float2half_rn(s0), h1v = __float2half_rn(s1);
                    __half h2 = __float2half_rn(s2), h3v = __float2half_rn(s3);
                    __half l0 = __float2half_rn(s0 - __half2float(h0));
                    __half l1 = __float2half_rn(s1 - __half2float(h1v));
                    __half l2 = __float2half_rn(s2 - __half2float(h2));
                    __half l3 = __float2half_rn(s3 - __half2float(h3v));
                    __half2 ph0 = __halves2half2(h0, h1v), ph1 = __halves2half2(h2, h3v);
                    __half2 pl0 = __halves2half2(l0, l1),  pl1 = __halves2half2(l2, l3);
                    uint2 hv = make_uint2(*(uint32_t*)&ph0, *(uint32_t*)&ph1);
                    uint2 lv = make_uint2(*(uint32_t*)&pl0, *(uint32_t*)&pl1);
                    *(uint2*)(hi_base + j * 8) = hv;
                    *(uint2*)(lo_base + j * 8) = lv;
                }
            }
            __syncthreads();

            // ---- GEMM: acc[2 mt][8 nt][4] += A_v @ W2, v in {hi, lo} ----
            float acc[2][8][4];
            #pragma unroll
            for (int mt = 0; mt < 2; mt++)
                #pragma unroll
                for (int nt = 0; nt < 8; nt++)
                    #pragma unroll
                    for (int c = 0; c < 4; c++) acc[mt][nt][c] = 0.0f;

            #pragma unroll 1
            for (int v = 0; v < 2; v++) {
                uint32_t a_addr = sb + (v ? SM_ALO : SM_AHI) + a_toff;
                uint32_t b_addr = b_base;
                #pragma unroll 4
                for (int ks = 0; ks < 16; ks++) {
                    uint32_t af0[4], af1[4];
                    ldsm_x4(af0, a_addr);
                    ldsm_x4(af1, a_addr + 16 * AROW);
                    #pragma unroll
                    for (int np = 0; np < 4; np++) {
                        uint32_t bf[4];
                        ldsm_x4(bf, b_addr + np * 16 * AROW);
                        mma16816(acc[0][np * 2 + 0], af0, bf + 0);
                        mma16816(acc[0][np * 2 + 1], af0, bf + 2);
                        mma16816(acc[1][np * 2 + 0], af1, bf + 0);
                        mma16816(acc[1][np * 2 + 1], af1, bf + 2);
                    }
                    a_addr += 32;
                    b_addr += 32;
                }
            }

            // ---- Epilogue: sin(30*z2 + 30*b2) . W3, reduce ----
            float p[2][2];
            #pragma unroll
            for (int mt = 0; mt < 2; mt++)
                #pragma unroll
                for (int rh = 0; rh < 2; rh++) {
                    float s = 0.0f;
                    #pragma unroll
                    for (int nt = 0; nt < 8; nt++) {
                        int c0 = rh * 2;
                        s = fmaf(__sinf(fmaf(30.0f, acc[mt][nt][c0],     b2r[nt*2+0])), w3r[nt*2+0], s);
                        s = fmaf(__sinf(fmaf(30.0f, acc[mt][nt][c0 + 1], b2r[nt*2+1])), w3r[nt*2+1], s);
                    }
                    p[mt][rh] = s;
                }
            #pragma unroll
            for (int msk = 1; msk < 4; msk <<= 1) {
                #pragma unroll
                for (int mt = 0; mt < 2; mt++)
                    #pragma unroll
                    for (int rh = 0; rh < 2; rh++)
                        p[mt][rh] += __shfl_xor_sync(0xffffffffu, p[mt][rh], msk);
            }
            if ((lane & 3) == 0) {
                #pragma unroll
                for (int mt = 0; mt < 2; mt++)
                    #pragma unroll
                    for (int rh = 0; rh < 2; rh++)
                        slots[ng * 64 + wm + mt * 16 + rh * 8 + (lane >> 2)] = p[mt][rh];
            }
            __syncthreads();

            if (tid < 64)
                zhalf[h] = slots[tid] + slots[64 + tid] + slots[128 + tid] + slots[192 + tid];
        }

        if (tid < 64) {
            float zf = zhalf[0], zc = zhalf[1];
            out[(size_t)bq * HW + pix0 + tid] = fmaf(tau, zc - zf, zf) + b3v;
        }
    }
}

// ---------------------------------------------------------------------------
extern "C" void kernel_launch(void* const* d_in, const int* in_sizes, int n_in,
                              void* d_out, int out_size)
{
    const float* x_real  = (const float*)d_in[0];
    const float* x_imag  = (const float*)d_in[1];
    const float* t_coord = (const float*)d_in[2];
    const float* enc_w   = (const float*)d_in[3];
    const float* enc_b   = (const float*)d_in[4];
    const float* W1      = (const float*)d_in[5];
    const float* b1      = (const float*)d_in[6];
    const float* W2      = (const float*)d_in[7];
    const float* b2      = (const float*)d_in[8];
    const float* W3      = (const float*)d_in[9];
    const float* b3      = (const float*)d_in[10];
    float*       out     = (float*)d_out;

    size_t smem1 = (3456 + 64 + 256 * 65) * sizeof(float);
    size_t smem2 = (64 * 68 + 64 * 256) * sizeof(float);
    cudaFuncSetAttribute(conv_kernel, cudaFuncAttributeMaxDynamicSharedMemorySize, (int)smem1);
    cudaFuncSetAttribute(proj_kernel, cudaFuncAttributeMaxDynamicSharedMemorySize, (int)smem2);
    cudaFuncSetAttribute(main_kernel, cudaFuncAttributeMaxDynamicSharedMemorySize, SM_TOT);

    prep_w2<<<256, 256>>>(W2);
    conv_kernel<<<2304, 256, smem1>>>(x_real, x_imag, enc_w, enc_b);
    proj_kernel<<<9216, 256, smem2>>>(W1, b1);
    main_kernel<<<148, 256, SM_TOT>>>(t_coord, W1, b2, W3, b3, out);
}

// round 6
// speedup vs baseline: 7.5925x; 1.9244x over previous
#include <cuda_runtime.h>
#include <cuda_fp16.h>
#include <cstdint>
#include <cstddef>

#define HW    9216      // 96*96
#define NCELL (2 * 32 * HW)   // 589824

// Scratch (device globals — allocation-free per harness rules)
__device__ float g_xenc[(size_t)NCELL * 64];       // conv output, channels-last
__device__ float g_A[(size_t)NCELL * 256];         // 30*(xenc @ W1[0:64] + b1)
__device__ __align__(16) __half g_w2h[256 * 264];  // W2^T fp16, [n][k] pad 264
__device__ __align__(16) __half g_w1h[256 * 72];   // W1[0:64]^T hi fp16, [n][k] pad 72
__device__ __align__(16) __half g_w1l[256 * 72];   // W1[0:64]^T lo fp16

// ---------------------------------------------------------------------------
// Helpers
// ---------------------------------------------------------------------------
__device__ __forceinline__ uint32_t smem_u32(const void* p) {
    uint32_t a;
    asm("{ .reg .u64 t; cvta.to.shared.u64 t, %1; cvt.u32.u64 %0, t; }" : "=r"(a) : "l"(p));
    return a;
}
__device__ __forceinline__ void ldsm_x4(uint32_t (&r)[4], uint32_t addr) {
    asm volatile("ldmatrix.sync.aligned.m8n8.x4.shared.b16 {%0,%1,%2,%3}, [%4];"
                 : "=r"(r[0]), "=r"(r[1]), "=r"(r[2]), "=r"(r[3]) : "r"(addr));
}
__device__ __forceinline__ void mma16816(float (&d)[4], const uint32_t (&a)[4],
                                         const uint32_t* b) {
    asm volatile("mma.sync.aligned.m16n8k16.row.col.f32.f16.f16.f32 "
                 "{%0,%1,%2,%3}, {%4,%5,%6,%7}, {%8,%9}, {%0,%1,%2,%3};"
                 : "+f"(d[0]), "+f"(d[1]), "+f"(d[2]), "+f"(d[3])
                 : "r"(a[0]), "r"(a[1]), "r"(a[2]), "r"(a[3]), "r"(b[0]), "r"(b[1]));
}

// ---------------------------------------------------------------------------
// Kernel 1: 3D conv (2 -> 64 channels, 3x3x3, SAME), output channels-last.
// ---------------------------------------------------------------------------
__global__ __launch_bounds__(256) void conv_kernel(
    const float* __restrict__ xr, const float* __restrict__ xi,
    const float* __restrict__ ew, const float* __restrict__ eb)
{
    extern __shared__ float sm[];
    float* ws   = sm;            // 3456
    float* bs   = ws + 3456;     // 64
    float* tile = bs + 64;       // 256 * 65

    int tid = threadIdx.x;
    for (int e = tid; e < 3456; e += 256) ws[e] = ew[e];
    if (tid < 64) bs[tid] = eb[tid];

    int blk = blockIdx.x;
    int bt  = blk / 36;
    int t36 = blk % 36;
    int t   = bt & 31;
    int b   = bt >> 5;
    int pix = t36 * 256 + tid;
    int h   = pix / 96;
    int w   = pix % 96;

    float v[54];
    {
        int e = 0;
        #pragma unroll
        for (int ch = 0; ch < 2; ch++) {
            const float* src = (ch == 0) ? xr : xi;
            #pragma unroll
            for (int dt = -1; dt <= 1; dt++) {
                int  tt  = t + dt;
                bool okt = (tt >= 0) && (tt < 32);
                #pragma unroll
                for (int dh = -1; dh <= 1; dh++) {
                    int  hh  = h + dh;
                    bool okh = okt && (hh >= 0) && (hh < 96);
                    #pragma unroll
                    for (int dw = -1; dw <= 1; dw++) {
                        int  ww = w + dw;
                        bool ok = okh && (ww >= 0) && (ww < 96);
                        v[e++] = ok ? src[(((size_t)(b * 32 + tt)) * 96 + hh) * 96 + ww] : 0.0f;
                    }
                }
            }
        }
    }
    __syncthreads();

    #pragma unroll 4
    for (int c = 0; c < 64; c++) {
        float acc = bs[c];
        #pragma unroll
        for (int q = 0; q < 54; q++) acc = fmaf(v[q], ws[c * 54 + q], acc);
        tile[tid * 65 + c] = acc;
    }
    __syncthreads();

    size_t outbase = ((size_t)bt * HW + (size_t)t36 * 256) * 64;
    for (int e = tid; e < 256 * 64; e += 256) {
        int p = e >> 6, c = e & 63;
        g_xenc[outbase + e] = tile[p * 65 + c];
    }
}

// ---------------------------------------------------------------------------
// Prep kernels: transpose weights into fp16 [n][k] padded layouts
// ---------------------------------------------------------------------------
__global__ void prep_w2(const float* __restrict__ W2)
{
    int idx = blockIdx.x * 256 + threadIdx.x;   // 65536
    int n = idx >> 8, k = idx & 255;
    g_w2h[n * 264 + k] = __float2half_rn(W2[k * 256 + n]);
}
__global__ void prep_w1(const float* __restrict__ W1)
{
    int n = blockIdx.x, k = threadIdx.x;        // 256 x 72
    float v = (k < 64) ? W1[k * 256 + n] : 0.0f;
    __half hi = __float2half_rn(v);
    g_w1h[n * 72 + k] = hi;
    g_w1l[n * 72 + k] = __float2half_rn(v - __half2float(hi));
}

// ---------------------------------------------------------------------------
// Kernel 2 (HMMA, persistent): A = 30 * (xenc @ W1[0:64,:] + b1)
// Per tile: 64 cells x 256 outs, K=64, 3-split fp16 (xh*Wh + xl*Wh + xh*Wl).
// ---------------------------------------------------------------------------
#define PROW 144              // bytes per [.,72-half] row
#define SMP_WH 0              // 256*144 = 36864
#define SMP_WL 36864
#define SMP_XH 73728          // 64*144 = 9216
#define SMP_XL 82944
#define SMP_TOT 92160

__global__ __launch_bounds__(256, 1) void proj_kernel(
    const float* __restrict__ b1)
{
    extern __shared__ char smem[];
    const uint32_t sb = smem_u32(smem);
    int tid  = threadIdx.x;
    int w    = tid >> 5;
    int lane = tid & 31;

    // Stage W1 hi/lo (resident)
    {
        const float4* s0 = (const float4*)g_w1h;
        const float4* s1 = (const float4*)g_w1l;
        float4* d0 = (float4*)(smem + SMP_WH);
        float4* d1 = (float4*)(smem + SMP_WL);
        for (int i = tid; i < 256 * 144 / 16; i += 256) { d0[i] = s0[i]; d1[i] = s1[i]; }
    }

    const int wm = (w & 1) * 32;       // 2 m-groups x 32 rows
    const int wn = (w >> 1) * 64;      // 4 n-groups x 64 cols

    float b1r[16];
    #pragma unroll
    for (int q = 0; q < 16; q++)
        b1r[q] = b1[wn + (q >> 1) * 8 + (lane & 3) * 2 + (q & 1)];

    const uint32_t a_toff = (uint32_t)(wm + (lane & 15)) * PROW + (uint32_t)(lane >> 4) * 16;
    const uint32_t b_toff = (uint32_t)(wn + (lane & 7) + ((lane >> 4) & 1) * 8) * PROW
                          + (uint32_t)((lane >> 3) & 1) * 16;

    const int lrow = tid >> 2;             // cell row this thread loads
    const int lk   = (tid & 3) * 16;       // 16 k values
    __syncthreads();

    for (int tile = blockIdx.x; tile < 9216; tile += 148) {
        size_t cell0 = (size_t)tile * 64;

        // Load + split xenc into smem
        {
            const float4* src = (const float4*)(g_xenc + (cell0 + lrow) * 64 + lk);
            char* hb = smem + SMP_XH + lrow * PROW + lk * 2;
            char* lb = smem + SMP_XL + lrow * PROW + lk * 2;
            #pragma unroll
            for (int c = 0; c < 2; c++) {
                float4 v0 = src[2 * c], v1 = src[2 * c + 1];
                float vv[8] = {v0.x, v0.y, v0.z, v0.w, v1.x, v1.y, v1.z, v1.w};
                uint32_t hv[4], lv[4];
                #pragma unroll
                for (int p = 0; p < 4; p++) {
                    __half h0 = __float2half_rn(vv[2*p]),   h1 = __float2half_rn(vv[2*p+1]);
                    __half l0 = __float2half_rn(vv[2*p]   - __half2float(h0));
                    __half l1 = __float2half_rn(vv[2*p+1] - __half2float(h1));
                    __half2 ph = __halves2half2(h0, h1), pl = __halves2half2(l0, l1);
                    hv[p] = *(uint32_t*)&ph;  lv[p] = *(uint32_t*)&pl;
                }
                *(uint4*)(hb + c * 16) = make_uint4(hv[0], hv[1], hv[2], hv[3]);
                *(uint4*)(lb + c * 16) = make_uint4(lv[0], lv[1], lv[2], lv[3]);
            }
        }
        __syncthreads();

        float acc[2][8][4];
        #pragma unroll
        for (int mt = 0; mt < 2; mt++)
            #pragma unroll
            for (int nt = 0; nt < 8; nt++)
                #pragma unroll
                for (int c = 0; c < 4; c++) acc[mt][nt][c] = 0.0f;

        const uint32_t abase[3] = {sb + SMP_XH, sb + SMP_XL, sb + SMP_XH};
        const uint32_t bbase[3] = {sb + SMP_WH, sb + SMP_WH, sb + SMP_WL};
        #pragma unroll
        for (int s = 0; s < 3; s++) {
            uint32_t a_addr = abase[s] + a_toff;
            uint32_t b_addr = bbase[s] + b_toff;
            #pragma unroll
            for (int ks = 0; ks < 4; ks++) {
                uint32_t af0[4], af1[4];
                ldsm_x4(af0, a_addr);
                ldsm_x4(af1, a_addr + 16 * PROW);
                #pragma unroll
                for (int np = 0; np < 4; np++) {
                    uint32_t bf[4];
                    ldsm_x4(bf, b_addr + np * 16 * PROW);
                    mma16816(acc[0][np * 2 + 0], af0, bf + 0);
                    mma16816(acc[0][np * 2 + 1], af0, bf + 2);
                    mma16816(acc[1][np * 2 + 0], af1, bf + 0);
                    mma16816(acc[1][np * 2 + 1], af1, bf + 2);
                }
                a_addr += 32;
                b_addr += 32;
            }
        }

        // Epilogue: A = 30*(z1 + b1), direct STG.64
        #pragma unroll
        for (int mt = 0; mt < 2; mt++) {
            int r0 = wm + mt * 16 + (lane >> 2);
            #pragma unroll
            for (int nt = 0; nt < 8; nt++) {
                int n0 = wn + nt * 8 + (lane & 3) * 2;
                float2 v0, v1;
                v0.x = 30.0f * (acc[mt][nt][0] + b1r[nt*2+0]);
                v0.y = 30.0f * (acc[mt][nt][1] + b1r[nt*2+1]);
                v1.x = 30.0f * (acc[mt][nt][2] + b1r[nt*2+0]);
                v1.y = 30.0f * (acc[mt][nt][3] + b1r[nt*2+1]);
                *(float2*)&g_A[(cell0 + r0)     * 256 + n0] = v0;
                *(float2*)&g_A[(cell0 + r0 + 8) * 256 + n0] = v1;
            }
        }
        __syncthreads();
    }
}

// ---------------------------------------------------------------------------
// Kernel 3: persistent HMMA SIREN, single-fp16 A, double-buffered.
// ---------------------------------------------------------------------------
#define AROW   528            // bytes per [.,264-half] row
#define SM_B    0             // 256*528 = 135168
#define SM_A0   135168        // 64*528  =  33792
#define SM_A1   168960        // 64*528  =  33792
#define SM_W1T  202752        // 1024
#define SM_SLOT 203776        // 512*4 = 2048
#define SM_TOT  205824

__global__ __launch_bounds__(256, 1) void main_kernel(
    const float* __restrict__ tcoord, const float* __restrict__ W1,
    const float* __restrict__ b2, const float* __restrict__ W3,
    const float* __restrict__ b3, float* __restrict__ out)
{
    extern __shared__ char smem[];
    const uint32_t sb = smem_u32(smem);
    int tid  = threadIdx.x;
    int w    = tid >> 5;
    int lane = tid & 31;

    // Stage W2 fp16 (resident) + w1 last row
    {
        const float4* src = (const float4*)g_w2h;
        float4*       dst = (float4*)(smem + SM_B);
        for (int i = tid; i < 256 * 528 / 16; i += 256) dst[i] = src[i];
    }
    float* w1t   = (float*)(smem + SM_W1T);
    float* slots = (float*)(smem + SM_SLOT);
    if (tid < 256) w1t[tid] = W1[64 * 256 + tid];
    __syncthreads();

    const float b3v = b3[0];

    const int wm = (w & 1) * 32;
    const int wn = (w >> 1) * 64;
    const int ng = w >> 1;

    float b2r[16], w3r[16];
    #pragma unroll
    for (int q = 0; q < 16; q++) {
        int n = wn + (q >> 1) * 8 + (lane & 3) * 2 + (q & 1);
        b2r[q] = 30.0f * b2[n];
        w3r[q] = W3[n];
    }

    const uint32_t a_toff = (uint32_t)(wm + (lane & 15)) * AROW + (uint32_t)(lane >> 4) * 16;
    const uint32_t b_toff = (uint32_t)(wn + (lane & 7) + ((lane >> 4) & 1) * 8) * AROW
                          + (uint32_t)((lane >> 3) & 1) * 16;
    const uint32_t b_base = sb + SM_B + b_toff;

    const int p1row = tid >> 2;          // phase-1 row
    const int p1k   = (tid & 3) * 64;    // phase-1 k start

    for (int tile = blockIdx.x; tile < 9216; tile += 148) {
        int bq = tile & 63, pt = tile >> 6;
        int b  = bq >> 5,  pix0 = pt * 64;

        float tc = tcoord[bq];
        tc = fminf(fmaxf(tc, -1.0f), 1.0f - 1e-6f);
        const float df = 2.0f / 31.0f;
        int   ti  = (int)floorf((tc + 1.0f) / df);
        float tau = (tc - (-1.0f + (float)ti * df)) / df;
        float ctc = 30.0f * tc;

        float acc[2][8][4];

        #pragma unroll 1
        for (int h = 0; h < 2; h++) {
            // ---- Phase 1: h1 = sin(A + ctc*w1t) -> fp16 into buf[h] ----
            {
                const float4* s4 = (const float4*)(
                    g_A + ((size_t)(b * 32 + ti + h) * HW + pix0 + p1row) * 256 + p1k);
                char* hb = smem + (h ? SM_A1 : SM_A0) + p1row * AROW + p1k * 2;
                #pragma unroll
                for (int j = 0; j < 8; j++) {
                    float4 a0 = s4[2*j], a1 = s4[2*j+1];
                    const float4 w0 = *(const float4*)&w1t[p1k + 8*j];
                    const float4 w1v = *(const float4*)&w1t[p1k + 8*j + 4];
                    float s[8];
                    s[0] = __sinf(fmaf(ctc, w0.x,  a0.x));
                    s[1] = __sinf(fmaf(ctc, w0.y,  a0.y));
                    s[2] = __sinf(fmaf(ctc, w0.z,  a0.z));
                    s[3] = __sinf(fmaf(ctc, w0.w,  a0.w));
                    s[4] = __sinf(fmaf(ctc, w1v.x, a1.x));
                    s[5] = __sinf(fmaf(ctc, w1v.y, a1.y));
                    s[6] = __sinf(fmaf(ctc, w1v.z, a1.z));
                    s[7] = __sinf(fmaf(ctc, w1v.w, a1.w));
                    uint32_t hv[4];
                    #pragma unroll
                    for (int p = 0; p < 4; p++) {
                        __half2 ph = __halves2half2(__float2half_rn(s[2*p]),
                                                    __float2half_rn(s[2*p+1]));
                        hv[p] = *(uint32_t*)&ph;
                    }
                    *(uint4*)(hb + j * 16) = make_uint4(hv[0], hv[1], hv[2], hv[3]);
                }
            }
            __syncthreads();

            // ---- GEMM: acc = h1 @ W2 ----
            #pragma unroll
            for (int mt = 0; mt < 2; mt++)
                #pragma unroll
                for (int nt = 0; nt < 8; nt++)
                    #pragma unroll
                    for (int c = 0; c < 4; c++) acc[mt][nt][c] = 0.0f;

            uint32_t a_addr = sb + (h ? SM_A1 : SM_A0) + a_toff;
            uint32_t b_addr = b_base;
            #pragma unroll 4
            for (int ks = 0; ks < 16; ks++) {
                uint32_t af0[4], af1[4];
                ldsm_x4(af0, a_addr);
                ldsm_x4(af1, a_addr + 16 * AROW);
                #pragma unroll
                for (int np = 0; np < 4; np++) {
                    uint32_t bf[4];
                    ldsm_x4(bf, b_addr + np * 16 * AROW);
                    mma16816(acc[0][np * 2 + 0], af0, bf + 0);
                    mma16816(acc[0][np * 2 + 1], af0, bf + 2);
                    mma16816(acc[1][np * 2 + 0], af1, bf + 0);
                    mma16816(acc[1][np * 2 + 1], af1, bf + 2);
                }
                a_addr += 32;
                b_addr += 32;
            }

            // ---- Epilogue: sin(30*z2 + 30*b2) . W3, reduce ----
            float p[2][2];
            #pragma unroll
            for (int mt = 0; mt < 2; mt++)
                #pragma unroll
                for (int rh = 0; rh < 2; rh++) {
                    float s = 0.0f;
                    #pragma unroll
                    for (int nt = 0; nt < 8; nt++) {
                        int c0 = rh * 2;
                        s = fmaf(__sinf(fmaf(30.0f, acc[mt][nt][c0],     b2r[nt*2+0])), w3r[nt*2+0], s);
                        s = fmaf(__sinf(fmaf(30.0f, acc[mt][nt][c0 + 1], b2r[nt*2+1])), w3r[nt*2+1], s);
                    }
                    p[mt][rh] = s;
                }
            #pragma unroll
            for (int msk = 1; msk < 4; msk <<= 1) {
                #pragma unroll
                for (int mt = 0; mt < 2; mt++)
                    #pragma unroll
                    for (int rh = 0; rh < 2; rh++)
                        p[mt][rh] += __shfl_xor_sync(0xffffffffu, p[mt][rh], msk);
            }
            if ((lane & 3) == 0) {
                #pragma unroll
                for (int mt = 0; mt < 2; mt++)
                    #pragma unroll
                    for (int rh = 0; rh < 2; rh++)
                        slots[h * 256 + ng * 64 + wm + mt * 16 + rh * 8 + (lane >> 2)] = p[mt][rh];
            }
        }
        __syncthreads();

        if (tid < 64) {
            float zf = slots[tid]       + slots[64 + tid]  + slots[128 + tid] + slots[192 + tid];
            float zc = slots[256 + tid] + slots[320 + tid] + slots[384 + tid] + slots[448 + tid];
            out[(size_t)bq * HW + pix0 + tid] = fmaf(tau, zc - zf, zf) + b3v;
        }
        __syncthreads();
    }
}

// ---------------------------------------------------------------------------
extern "C" void kernel_launch(void* const* d_in, const int* in_sizes, int n_in,
                              void* d_out, int out_size)
{
    const float* x_real  = (const float*)d_in[0];
    const float* x_imag  = (const float*)d_in[1];
    const float* t_coord = (const float*)d_in[2];
    const float* enc_w   = (const float*)d_in[3];
    const float* enc_b   = (const float*)d_in[4];
    const float* W1      = (const float*)d_in[5];
    const float* b1      = (const float*)d_in[6];
    const float* W2      = (const float*)d_in[7];
    const float* b2      = (const float*)d_in[8];
    const float* W3      = (const float*)d_in[9];
    const float* b3      = (const float*)d_in[10];
    float*       out     = (float*)d_out;

    size_t smem1 = (3456 + 64 + 256 * 65) * sizeof(float);
    cudaFuncSetAttribute(conv_kernel, cudaFuncAttributeMaxDynamicSharedMemorySize, (int)smem1);
    cudaFuncSetAttribute(proj_kernel, cudaFuncAttributeMaxDynamicSharedMemorySize, SMP_TOT);
    cudaFuncSetAttribute(main_kernel, cudaFuncAttributeMaxDynamicSharedMemorySize, SM_TOT);

    prep_w2<<<256, 256>>>(W2);
    prep_w1<<<256, 72>>>(W1);
    conv_kernel<<<2304, 256, smem1>>>(x_real, x_imag, enc_w, enc_b);
    proj_kernel<<<148, 256, SMP_TOT>>>(b1);
    main_kernel<<<148, 256, SM_TOT>>>(t_coord, W1, b2, W3, b3, out);
}